// round 3
// baseline (speedup 1.0000x reference)
#include <cuda_runtime.h>
#include <math.h>

// ---------------- problem constants ----------------
#define NCLS   80
#define NTGT   512
#define NA     3
#define NOFF   5
#define NB     16

// level sizes
#define HW0    6400   // 80x80
#define HW1    1600   // 40x40
#define HW2    400    // 20x20
#define CELLS0 (NB*NA*HW0)   // 307200
#define CELLS1 (NB*NA*HW1)   // 76800
#define CELLS2 (NB*NA*HW2)   // 19200
#define CELLS_TOTAL (CELLS0+CELLS1+CELLS2)  // 403200

#define ENTRIES_PER_LEVEL (NOFF*NA*NTGT)    // 7680
#define ENTRIES_TOTAL     (3*ENTRIES_PER_LEVEL) // 23040

// ---------------- scratch (no allocations allowed) ----------------
__device__ float  g_objgt[CELLS_TOTAL];
// per level: [box_sum, cnt, cls_sum, obj_sum]
__device__ double g_acc[12];

__constant__ float c_anchors[3][NA][2] = {
    {{10.f,13.f},{16.f,30.f},{33.f,23.f}},
    {{30.f,61.f},{62.f,45.f},{59.f,119.f}},
    {{116.f,90.f},{156.f,198.f},{373.f,326.f}}
};
__constant__ float c_offx[NOFF] = {0.f, 0.5f, 0.f, -0.5f, 0.f};
__constant__ float c_offy[NOFF] = {0.f, 0.f, 0.5f, 0.f, -0.5f};

__device__ __forceinline__ float bce_logits(float x, float z) {
    return fmaxf(x, 0.f) - x * z + log1pf(expf(-fabsf(x)));
}
__device__ __forceinline__ float sigmoidf_(float x) {
    return 1.f / (1.f + expf(-x));
}

// ---------------- kernel 1: zero scratch ----------------
__global__ void yolo_zero_kernel() {
    int i = blockIdx.x * blockDim.x + threadIdx.x;
    if (i < CELLS_TOTAL) g_objgt[i] = 0.f;
    if (i < 12) g_acc[i] = 0.0;
}

// ---------------- kernel 2: per-entry box/cls + obj_gt scatter ----------------
// one warp per (level, offset, anchor, target) entry
__global__ void yolo_entry_kernel(const float* __restrict__ p0,
                                  const float* __restrict__ p1,
                                  const float* __restrict__ p2,
                                  const float* __restrict__ tgt) {
    int gwid = (blockIdx.x * blockDim.x + threadIdx.x) >> 5;
    int lane = threadIdx.x & 31;
    if (gwid >= ENTRIES_TOTAL) return;

    int level = gwid / ENTRIES_PER_LEVEL;
    int e     = gwid % ENTRIES_PER_LEVEL;
    int o = e / (NA * NTGT);
    int a = (e / NTGT) % NA;
    int n = e % NTGT;

    int Wd, HW, scoff;
    const float* layer;
    if (level == 0)      { Wd = 80; HW = HW0; scoff = 0;               layer = p0; }
    else if (level == 1) { Wd = 40; HW = HW1; scoff = CELLS0;          layer = p1; }
    else                 { Wd = 20; HW = HW2; scoff = CELLS0 + CELLS1; layer = p2; }
    float Wf = (float)Wd;

    const float* t = tgt + n * 6;
    float tx = t[2] * Wf;
    float ty = t[3] * Wf;   // H == W per level
    float tw = t[4] * Wf;
    float th = t[5] * Wf;

    float aw = c_anchors[level][a][0];
    float ah = c_anchors[level][a][1];

    // anchor-ratio selection
    float rw = tw / aw, rh = th / ah;
    float m = fmaxf(fmaxf(rw, 1.f / rw), fmaxf(rh, 1.f / rh));
    bool sel = (m < 4.0f);

    // offset condition
    float xmod = fmodf(tx, 1.0f);
    float ymod = fmodf(ty, 1.0f);
    bool cond;
    switch (o) {
        case 0: cond = true; break;
        case 1: cond = (xmod < 0.5f) && (tx > 1.0f); break;
        case 2: cond = (ymod < 0.5f) && (ty > 1.0f); break;
        case 3: cond = (xmod > 0.5f) && (tx < Wf - 1.0f); break;
        default: cond = (ymod > 0.5f) && (ty < Wf - 1.0f); break;
    }
    if (!(sel && cond)) return;   // warp-uniform

    int grid_x = (int)(tx - c_offx[o]);
    int grid_y = (int)(ty - c_offy[o]);
    float gxyx = tx - (float)grid_x;   // uses UNclipped grid (matches ref)
    float gxyy = ty - (float)grid_y;
    int gx = min(max(grid_x, 0), Wd - 1);
    int gy = min(max(grid_y, 0), Wd - 1);

    int im = (int)t[0];
    int ci = (int)t[1];

    int base = ((im * 255 + a * 85) * HW) + gy * Wd + gx;

    // class loss: lanes split the 80 channels
    float csum = 0.f;
    for (int j = lane; j < NCLS; j += 32) {
        float x = layer[base + (5 + j) * HW];
        csum += bce_logits(x, (j == ci) ? 1.0f : 0.0f);
    }
    #pragma unroll
    for (int s = 16; s > 0; s >>= 1)
        csum += __shfl_xor_sync(0xffffffffu, csum, s);

    if (lane == 0) {
        float op0 = layer[base];
        float op1 = layer[base + HW];
        float op2 = layer[base + 2 * HW];
        float op3 = layer[base + 3 * HW];

        float px = sigmoidf_(op0) * 2.0f - 0.5f;
        float py = sigmoidf_(op1) * 2.0f - 0.5f;
        float sw = sigmoidf_(op2) * 2.0f;
        float sh = sigmoidf_(op3) * 2.0f;
        float pw = sw * sw * aw;
        float ph = sh * sh * ah;

        // GIoU between (px,py,pw,ph) and (gxyx,gxyy,tw,th)
        float ax0 = px - pw * 0.5f, ax1 = px + pw * 0.5f;
        float ay0 = py - ph * 0.5f, ay1 = py + ph * 0.5f;
        float bx0 = gxyx - tw * 0.5f, bx1 = gxyx + tw * 0.5f;
        float by0 = gxyy - th * 0.5f, by1 = gxyy + th * 0.5f;
        float iw = fmaxf(fminf(ax1, bx1) - fmaxf(ax0, bx0), 0.0f);
        float ih = fmaxf(fminf(ay1, by1) - fmaxf(ay0, by0), 0.0f);
        float inter = iw * ih;
        float uni = (ax1 - ax0) * (ay1 - ay0) + (bx1 - bx0) * (by1 - by0) - inter;
        float iou = inter / uni;
        float cw = fmaxf(ax1, bx1) - fminf(ax0, bx0) + 1e-16f;
        float ch = fmaxf(ay1, by1) - fminf(ay0, by0);
        float carea = cw * ch + 1e-16f;
        float giou = iou - (carea - uni) / carea;

        atomicAdd(&g_acc[level * 4 + 0], (double)(1.0f - giou));
        atomicAdd(&g_acc[level * 4 + 1], 1.0);
        atomicAdd(&g_acc[level * 4 + 2], (double)csum);

        // scatter clip(giou,0): nonneg float bits are order-monotone -> uint max
        float gval = fmaxf(giou, 0.0f);
        int sc = scoff + ((im * NA + a) * Wd + gy) * Wd + gx;
        atomicMax((unsigned int*)&g_objgt[sc], __float_as_uint(gval));
    }
}

// ---------------- kernel 3: objectness BCE over all cells ----------------
// level sizes all divisible by 256 -> each block is level-pure
__global__ void yolo_obj_kernel(const float* __restrict__ p0,
                                const float* __restrict__ p1,
                                const float* __restrict__ p2) {
    __shared__ float s_part[8];
    int i = blockIdx.x * blockDim.x + threadIdx.x;
    int level, cell, HW;
    const float* layer;
    if (i < CELLS0)                { level = 0; cell = i;                 HW = HW0; layer = p0; }
    else if (i < CELLS0 + CELLS1)  { level = 1; cell = i - CELLS0;        HW = HW1; layer = p1; }
    else                           { level = 2; cell = i - CELLS0-CELLS1; HW = HW2; layer = p2; }

    int b  = cell / (NA * HW);
    int r  = cell % (NA * HW);
    int a  = r / HW;
    int hw = r % HW;
    float x = layer[(b * 255 + a * 85 + 4) * HW + hw];
    float g = g_objgt[i];
    float v = bce_logits(x, g);

    // block reduce
    #pragma unroll
    for (int s = 16; s > 0; s >>= 1)
        v += __shfl_xor_sync(0xffffffffu, v, s);
    int lane = threadIdx.x & 31;
    int warp = threadIdx.x >> 5;
    if (lane == 0) s_part[warp] = v;
    __syncthreads();
    if (warp == 0) {
        float bsum = (lane < 8) ? s_part[lane] : 0.f;
        #pragma unroll
        for (int s = 4; s > 0; s >>= 1)
            bsum += __shfl_xor_sync(0xffffffffu, bsum, s);
        if (lane == 0)
            atomicAdd(&g_acc[level * 4 + 3], (double)bsum);
    }
}

// ---------------- kernel 4: finalize ----------------
__global__ void yolo_final_kernel(float* __restrict__ out) {
    const double bal[3]   = {4.0, 1.0, 0.4};
    const double cells[3] = {(double)CELLS0, (double)CELLS1, (double)CELLS2};
    double lbox = 0.0, lobj = 0.0, lcls = 0.0;
    for (int l = 0; l < 3; l++) {
        double cnt = g_acc[l * 4 + 1];
        if (cnt > 0.0) {
            lbox += g_acc[l * 4 + 0] / cnt;
            lcls += g_acc[l * 4 + 2] / (cnt * (double)NCLS);
        }
        lobj += bal[l] * (g_acc[l * 4 + 3] / cells[l]);
    }
    // BOX_W=0.05, OBJ_W=1.0, CLS_W=0.5*NC/80=0.5, scale=1, batch=16
    double loss = (0.05 * lbox + 1.0 * lobj + 0.5 * lcls) * (double)NB;
    out[0] = (float)loss;
}

// ---------------- launch ----------------
extern "C" void kernel_launch(void* const* d_in, const int* in_sizes, int n_in,
                              void* d_out, int out_size) {
    const float* p0  = (const float*)d_in[0];
    const float* p1  = (const float*)d_in[1];
    const float* p2  = (const float*)d_in[2];
    const float* tgt = (const float*)d_in[3];
    float* out = (float*)d_out;

    yolo_zero_kernel<<<(CELLS_TOTAL + 255) / 256, 256>>>();
    yolo_entry_kernel<<<(ENTRIES_TOTAL * 32 + 255) / 256, 256>>>(p0, p1, p2, tgt);
    yolo_obj_kernel<<<CELLS_TOTAL / 256, 256>>>(p0, p1, p2);
    yolo_final_kernel<<<1, 1>>>(out);
}